// round 2
// baseline (speedup 1.0000x reference)
#include <cuda_runtime.h>
#include <math.h>

#define N_NODES      100000
#define HIDDEN       256
#define K_CLUSTERS   20
#define CLUSTER_SIZE 5000
#define BLOCKS_PER_CLUSTER 40
#define ROWS_PER_BLOCK (CLUSTER_SIZE / BLOCKS_PER_CLUSTER)   // 125
#define NWARPS 8

// Scratch (allocation-free rule: __device__ globals)
__device__ float g_partial[K_CLUSTERS * BLOCKS_PER_CLUSTER * HIDDEN]; // ~800 KB
__device__ float g_wc[K_CLUSTERS * HIDDEN];
__device__ float g_accum;

__device__ __forceinline__ float softplus_f(float x) {
    // stable: max(x,0) + log1p(exp(-|x|))
    return fmaxf(x, 0.0f) + log1pf(__expf(-fabsf(x)));
}

// Pass 1: per-(cluster, block) partial column sums of gathered h1 rows.
__global__ void __launch_bounds__(HIDDEN)
k_partial_sum(const float* __restrict__ h1, const int* __restrict__ ci) {
    const int k = blockIdx.y;
    const int b = blockIdx.x;
    const int d = threadIdx.x;
    const int* idx = ci + k * CLUSTER_SIZE + b * ROWS_PER_BLOCK;

    float acc = 0.0f;
    #pragma unroll 5
    for (int n = 0; n < ROWS_PER_BLOCK; ++n) {
        long long r = (long long)idx[n];       // uniform (broadcast) load
        acc += h1[r * HIDDEN + d];             // coalesced 1KB row read
    }
    g_partial[(k * BLOCKS_PER_CLUSTER + b) * HIDDEN + d] = acc;
}

// Pass 2: reduce partials -> mean -> sigmoid -> c; Wc = W @ c. One block per cluster.
__global__ void __launch_bounds__(HIDDEN)
k_make_wc(const float* __restrict__ W) {
    const int k = blockIdx.x;
    const int d = threadIdx.x;
    __shared__ float c_s[HIDDEN];

    float s = 0.0f;
    #pragma unroll
    for (int b = 0; b < BLOCKS_PER_CLUSTER; ++b)
        s += g_partial[(k * BLOCKS_PER_CLUSTER + b) * HIDDEN + d];

    float m = s * (1.0f / (float)CLUSTER_SIZE);
    c_s[d] = 1.0f / (1.0f + __expf(-m));       // sigmoid
    __syncthreads();

    // Wc[d] = sum_e W[d,e] * c[e]
    const float4* Wr = reinterpret_cast<const float4*>(W + (long long)d * HIDDEN);
    const float4* c4 = reinterpret_cast<const float4*>(c_s);
    float wc = 0.0f;
    #pragma unroll 8
    for (int e = 0; e < HIDDEN / 4; ++e) {
        float4 w4 = Wr[e];
        float4 cc = c4[e];
        wc += w4.x * cc.x + w4.y * cc.y + w4.z * cc.z + w4.w * cc.w;
    }
    g_wc[k * HIDDEN + d] = wc;

    if (k == 0 && d == 0) g_accum = 0.0f;      // runs before pass 3 in-stream
}

// Pass 3: per-row bilinear scores + softplus, warp per row.
__global__ void __launch_bounds__(HIDDEN)
k_scores(const float* __restrict__ h1, const float* __restrict__ h2,
         const int* __restrict__ ci, const float* __restrict__ bptr) {
    const int k    = blockIdx.y;
    const int blk  = blockIdx.x;
    const int tid  = threadIdx.x;
    const int w    = tid >> 5;
    const int lane = tid & 31;

    __shared__ float wc_s[HIDDEN];
    __shared__ float warp_acc[NWARPS];

    wc_s[tid] = g_wc[k * HIDDEN + tid];
    __syncthreads();

    const float bb = *bptr;
    const float4* wc4 = reinterpret_cast<const float4*>(wc_s);
    const float4 wa = wc4[lane];
    const float4 wb = wc4[lane + 32];

    const int* idx = ci + k * CLUSTER_SIZE + blk * ROWS_PER_BLOCK;

    float acc = 0.0f;
    for (int n = w; n < ROWS_PER_BLOCK; n += NWARPS) {
        long long r = (long long)idx[n];
        const float4* r1 = reinterpret_cast<const float4*>(h1 + r * HIDDEN);
        const float4* r2 = reinterpret_cast<const float4*>(h2 + r * HIDDEN);
        float4 a0 = r1[lane];
        float4 a1 = r1[lane + 32];
        float4 b0 = r2[lane];
        float4 b1 = r2[lane + 32];

        float s1 = a0.x * wa.x + a0.y * wa.y + a0.z * wa.z + a0.w * wa.w
                 + a1.x * wb.x + a1.y * wb.y + a1.z * wb.z + a1.w * wb.w;
        float s2 = b0.x * wa.x + b0.y * wa.y + b0.z * wa.z + b0.w * wa.w
                 + b1.x * wb.x + b1.y * wb.y + b1.z * wb.z + b1.w * wb.w;

        #pragma unroll
        for (int o = 16; o > 0; o >>= 1) {
            s1 += __shfl_xor_sync(0xFFFFFFFFu, s1, o);
            s2 += __shfl_xor_sync(0xFFFFFFFFu, s2, o);
        }
        s1 += bb;
        s2 += bb;
        // positives: softplus(-sc1); negatives: softplus(sc2)
        acc += softplus_f(-s1) + softplus_f(s2);
    }

    if (lane == 0) warp_acc[w] = acc;
    __syncthreads();
    if (tid == 0) {
        float t = 0.0f;
        #pragma unroll
        for (int i = 0; i < NWARPS; ++i) t += warp_acc[i];
        atomicAdd(&g_accum, t);
    }
}

__global__ void k_finalize(float* __restrict__ out) {
    // loss = 0.5 * sum / (K * CLUSTER_SIZE)
    out[0] = g_accum * (0.5f / (float)(K_CLUSTERS * CLUSTER_SIZE));
}

extern "C" void kernel_launch(void* const* d_in, const int* in_sizes, int n_in,
                              void* d_out, int out_size) {
    const float* h1 = (const float*)d_in[0];
    const float* h2 = (const float*)d_in[1];
    const int*   ci = (const int*)d_in[2];
    const float* W  = (const float*)d_in[3];
    const float* b  = (const float*)d_in[4];
    float* out = (float*)d_out;

    dim3 gridA(BLOCKS_PER_CLUSTER, K_CLUSTERS);
    k_partial_sum<<<gridA, HIDDEN>>>(h1, ci);
    k_make_wc<<<K_CLUSTERS, HIDDEN>>>(W);
    k_scores<<<gridA, HIDDEN>>>(h1, h2, ci, b);
    k_finalize<<<1, 1>>>(out);
}